// round 2
// baseline (speedup 1.0000x reference)
#include <cuda_runtime.h>

// ---------------------------------------------------------------------------
// GTN forward, sparse-aware, round 2.
//   Phase1 (one kernel, concurrent roles):
//     blocks [0,2048):   softmax weights (in-block) + sparsify A rows
//     blocks [2048,2304): XW = X @ Wg  (32x64 tiles)
//   k_y:    Y[c] = A2[c] @ XW   (unrolled-by-4 sparse gather)
//   k_final: dense smem H row via warp-parallel scatter, threshold/degree,
//            out = relu(coef * (A1 . Y - dropped corrections) + bg)
// ---------------------------------------------------------------------------

#define NN 2048
#define NE 4
#define NC 2
#define WIN 512
#define WOUT 256
#define CAP 128
#define MAXDROP 256
#define THRESH 0.05f
#define WEPS 1e-4f

#define GEMM_MT 32
#define GEMM_NT 64
#define GEMM_BLOCKS ((NN / GEMM_MT) * (WOUT / GEMM_NT))   // 64*4 = 256

// Scratch (device globals; no allocations allowed)
__device__ int   g_nnz[NN];
__device__ int   g_cols[NN * CAP];
__device__ float g_a1[NN * CAP * NC];   // [(row*CAP+slot)*2 + c]
__device__ float g_a2[NN * CAP * NC];
__device__ float g_XW[NN * WOUT];
__device__ float g_Y[NC][NN * WOUT];

// ---------------------------------------------------------------- phase 1
struct P1Smem {
    union {
        struct {
            float As[16][GEMM_MT];
            float Bs[16][GEMM_NT];
        } g;
        struct {
            int   cnt;
            float f1[NC][NE];
            float f2[NC][NE];
        } s;
    } u;
};

__global__ void k_phase1(const float* __restrict__ A,
                         const float* __restrict__ X,
                         const float* __restrict__ Wg,
                         const float* __restrict__ W1a,
                         const float* __restrict__ W1b) {
    __shared__ P1Smem sm;
    const int tid = threadIdx.x;

    if (blockIdx.x < NN) {
        // ------------------------------------------- sparsify role
        const int i = blockIdx.x;
        if (tid == 0) {
            sm.u.s.cnt = 0;
            // softmax over edge dim, threshold < 1e-4 -> 0 (redundant per
            // block, deterministic, trivially cheap)
            for (int c = 0; c < NC; c++) {
                float m = -1e30f;
                for (int e = 0; e < NE; e++) m = fmaxf(m, W1a[c * NE + e]);
                float ex[NE], s = 0.f;
                for (int e = 0; e < NE; e++) { ex[e] = expf(W1a[c * NE + e] - m); s += ex[e]; }
                for (int e = 0; e < NE; e++) {
                    float f = ex[e] / s;
                    sm.u.s.f1[c][e] = (f < WEPS) ? 0.f : f;
                }
                m = -1e30f;
                for (int e = 0; e < NE; e++) m = fmaxf(m, W1b[c * NE + e]);
                s = 0.f;
                for (int e = 0; e < NE; e++) { ex[e] = expf(W1b[c * NE + e] - m); s += ex[e]; }
                for (int e = 0; e < NE; e++) {
                    float f = ex[e] / s;
                    sm.u.s.f2[c][e] = (f < WEPS) ? 0.f : f;
                }
            }
        }
        __syncthreads();

        const size_t planeStride = (size_t)NN * NN;
        const float* base = A + (size_t)i * NN;

        #pragma unroll
        for (int g = 0; g < 2; g++) {
            int j0 = tid * 4 + g * 1024;
            float4 v[NE];
            #pragma unroll
            for (int e = 0; e < NE; e++)
                v[e] = *(const float4*)(base + (size_t)e * planeStride + j0);

            #pragma unroll
            for (int l = 0; l < 4; l++) {
                float a[NE];
                a[0] = l == 0 ? v[0].x : l == 1 ? v[0].y : l == 2 ? v[0].z : v[0].w;
                a[1] = l == 0 ? v[1].x : l == 1 ? v[1].y : l == 2 ? v[1].z : v[1].w;
                a[2] = l == 0 ? v[2].x : l == 1 ? v[2].y : l == 2 ? v[2].z : v[2].w;
                a[3] = l == 0 ? v[3].x : l == 1 ? v[3].y : l == 2 ? v[3].z : v[3].w;
                bool nz = (a[0] != 0.f) | (a[1] != 0.f) | (a[2] != 0.f) | (a[3] != 0.f);
                if (nz) {
                    int slot = atomicAdd(&sm.u.s.cnt, 1);
                    if (slot < CAP) {
                        int idx = i * CAP + slot;
                        g_cols[idx] = j0 + l;
                        #pragma unroll
                        for (int c = 0; c < NC; c++) {
                            g_a1[idx * 2 + c] =
                                sm.u.s.f1[c][0] * a[0] + sm.u.s.f1[c][1] * a[1] +
                                sm.u.s.f1[c][2] * a[2] + sm.u.s.f1[c][3] * a[3];
                            g_a2[idx * 2 + c] =
                                sm.u.s.f2[c][0] * a[0] + sm.u.s.f2[c][1] * a[1] +
                                sm.u.s.f2[c][2] * a[2] + sm.u.s.f2[c][3] * a[3];
                        }
                    }
                }
            }
        }
        __syncthreads();
        if (tid == 0) g_nnz[i] = min(sm.u.s.cnt, CAP);
    } else {
        // ------------------------------------------- GEMM role: XW = X @ Wg
        const int b  = blockIdx.x - NN;
        const int bm = (b >> 2) * GEMM_MT;       // 64 m-tiles
        const int bn = (b & 3) * GEMM_NT;        // 4 n-tiles
        const int tx = tid & 15;                 // n / 4
        const int ty = tid >> 4;                 // m / 2
        float acc[2][4] = {};

        for (int k0 = 0; k0 < WIN; k0 += 16) {
            #pragma unroll
            for (int t = 0; t < 2; t++) {
                int idx = tid + t * 256;
                int m = idx >> 4, kk = idx & 15;
                sm.u.g.As[kk][m] = X[(size_t)(bm + m) * WIN + k0 + kk];
            }
            #pragma unroll
            for (int t = 0; t < 4; t++) {
                int idx = tid + t * 256;
                int kk = idx >> 6, n = idx & 63;
                sm.u.g.Bs[kk][n] = Wg[(size_t)(k0 + kk) * WOUT + bn + n];
            }
            __syncthreads();
            #pragma unroll
            for (int k = 0; k < 16; k++) {
                float a0 = sm.u.g.As[k][ty * 2 + 0];
                float a1 = sm.u.g.As[k][ty * 2 + 1];
                float4 b4 = *(const float4*)&sm.u.g.Bs[k][tx * 4];
                acc[0][0] = fmaf(a0, b4.x, acc[0][0]);
                acc[0][1] = fmaf(a0, b4.y, acc[0][1]);
                acc[0][2] = fmaf(a0, b4.z, acc[0][2]);
                acc[0][3] = fmaf(a0, b4.w, acc[0][3]);
                acc[1][0] = fmaf(a1, b4.x, acc[1][0]);
                acc[1][1] = fmaf(a1, b4.y, acc[1][1]);
                acc[1][2] = fmaf(a1, b4.z, acc[1][2]);
                acc[1][3] = fmaf(a1, b4.w, acc[1][3]);
            }
            __syncthreads();
        }
        #pragma unroll
        for (int u = 0; u < 2; u++) {
            float4 o = make_float4(acc[u][0], acc[u][1], acc[u][2], acc[u][3]);
            *(float4*)&g_XW[(size_t)(bm + ty * 2 + u) * WOUT + bn + tx * 4] = o;
        }
    }
}

// ---------------------------------------------------------------- kernel y
// Y[c][k][:] = sum_s a2[c][k][s] * XW[col[s]][:]   (unroll-by-4 gather)
__global__ void k_y() {
    const int k = blockIdx.x;
    const int f = threadIdx.x;          // 256 threads = feature
    __shared__ int   scol[CAP];
    __shared__ float sv0[CAP], sv1[CAP];
    const int n2 = g_nnz[k];
    for (int s = f; s < n2; s += 256) {
        int idx = k * CAP + s;
        scol[s] = g_cols[idx] * WOUT;
        sv0[s] = g_a2[idx * 2 + 0];
        sv1[s] = g_a2[idx * 2 + 1];
    }
    __syncthreads();
    float acc0 = 0.f, acc1 = 0.f;
    int s = 0;
    for (; s + 4 <= n2; s += 4) {
        float x0 = g_XW[scol[s + 0] + f];
        float x1 = g_XW[scol[s + 1] + f];
        float x2 = g_XW[scol[s + 2] + f];
        float x3 = g_XW[scol[s + 3] + f];
        acc0 = fmaf(sv0[s + 0], x0, acc0);
        acc1 = fmaf(sv1[s + 0], x0, acc1);
        acc0 = fmaf(sv0[s + 1], x1, acc0);
        acc1 = fmaf(sv1[s + 1], x1, acc1);
        acc0 = fmaf(sv0[s + 2], x2, acc0);
        acc1 = fmaf(sv1[s + 2], x2, acc1);
        acc0 = fmaf(sv0[s + 3], x3, acc0);
        acc1 = fmaf(sv1[s + 3], x3, acc1);
    }
    for (; s < n2; s++) {
        float x = g_XW[scol[s] + f];
        acc0 = fmaf(sv0[s], x, acc0);
        acc1 = fmaf(sv1[s], x, acc1);
    }
    g_Y[0][(size_t)k * WOUT + f] = acc0;
    g_Y[1][(size_t)k * WOUT + f] = acc1;
}

// ---------------------------------------------------------------- kernel final
__global__ void k_final(const float* __restrict__ bg, float* __restrict__ out) {
    const int i = blockIdx.x;
    const int tid = threadIdx.x;        // 256
    const int warp = tid >> 5, lane = tid & 31;

    __shared__ float H0[NN], H1[NN];    // 16 KB dense row accumulators
    __shared__ int   c1s[CAP];
    __shared__ float w0s[CAP], w1s[CAP];
    __shared__ float degsh[NC];
    __shared__ int   dropn[NC];
    __shared__ int   dropj[NC][MAXDROP];
    __shared__ float droph[NC][MAXDROP];

    float4 z = make_float4(0.f, 0.f, 0.f, 0.f);
    for (int t = tid; t < NN / 4; t += 256) {
        ((float4*)H0)[t] = z;
        ((float4*)H1)[t] = z;
    }
    if (tid < NC) { degsh[tid] = 0.f; dropn[tid] = 0; }
    const int n1 = g_nnz[i];
    for (int s = tid; s < n1; s += 256) {
        int idx = i * CAP + s;
        c1s[s] = g_cols[idx];
        w0s[s] = g_a1[idx * 2 + 0];
        w1s[s] = g_a1[idx * 2 + 1];
    }
    __syncthreads();

    // scatter: one warp per source slot s, lanes over target slots s2
    for (int s = warp; s < n1; s += 8) {
        int k = c1s[s];
        int n2 = g_nnz[k];
        float w0 = w0s[s], w1 = w1s[s];
        for (int s2 = lane; s2 < n2; s2 += 32) {
            int idx = k * CAP + s2;
            int j = g_cols[idx];
            float h0 = w0 * g_a2[idx * 2 + 0];
            float h1 = w1 * g_a2[idx * 2 + 1];
            if (h0 != 0.f) atomicAdd(&H0[j], h0);
            if (h1 != 0.f) atomicAdd(&H1[j], h1);
        }
    }
    __syncthreads();

    // threshold scan: degree sums + dropped-entry lists
    float d0 = 0.f, d1 = 0.f;
    for (int j = tid; j < NN; j += 256) {
        float h0 = H0[j];
        if (h0 > THRESH) d0 += h0;
        else if (h0 > 0.f) {
            int p = atomicAdd(&dropn[0], 1);
            if (p < MAXDROP) { dropj[0][p] = j; droph[0][p] = h0; }
        }
        float h1 = H1[j];
        if (h1 > THRESH) d1 += h1;
        else if (h1 > 0.f) {
            int p = atomicAdd(&dropn[1], 1);
            if (p < MAXDROP) { dropj[1][p] = j; droph[1][p] = h1; }
        }
    }
    #pragma unroll
    for (int o = 16; o > 0; o >>= 1) {
        d0 += __shfl_down_sync(0xffffffff, d0, o);
        d1 += __shfl_down_sync(0xffffffff, d1, o);
    }
    if (lane == 0) {
        if (d0 != 0.f) atomicAdd(&degsh[0], d0);
        if (d1 != 0.f) atomicAdd(&degsh[1], d1);
    }
    __syncthreads();

    float coef[NC];
    #pragma unroll
    for (int c = 0; c < NC; c++) {
        float deg = degsh[c];
        if (deg > 0.f) {
            float dinv = 1.f / deg;
            float deg2 = deg * dinv;      // double row-normalization
            coef[c] = dinv * (1.f / deg2);
        } else {
            coef[c] = 0.f;
        }
    }

    // output: feature f = tid, unroll-by-4 sparse gather of Y rows
    const int f = tid;
    const float bias = bg[f];
    #pragma unroll
    for (int c = 0; c < NC; c++) {
        const float* Yc = g_Y[c];
        const float* ws = (c == 0) ? w0s : w1s;
        float acc = 0.f;
        int s = 0;
        for (; s + 4 <= n1; s += 4) {
            float y0 = Yc[(size_t)c1s[s + 0] * WOUT + f];
            float y1 = Yc[(size_t)c1s[s + 1] * WOUT + f];
            float y2 = Yc[(size_t)c1s[s + 2] * WOUT + f];
            float y3 = Yc[(size_t)c1s[s + 3] * WOUT + f];
            acc = fmaf(ws[s + 0], y0, acc);
            acc = fmaf(ws[s + 1], y1, acc);
            acc = fmaf(ws[s + 2], y2, acc);
            acc = fmaf(ws[s + 3], y3, acc);
        }
        for (; s < n1; s++)
            acc = fmaf(ws[s], Yc[(size_t)c1s[s] * WOUT + f], acc);

        int nd = min(dropn[c], MAXDROP);
        for (int d = 0; d < nd; d++)
            acc -= droph[c][d] * g_XW[(size_t)dropj[c][d] * WOUT + f];

        float o = coef[c] * acc + bias;
        out[(size_t)i * (NC * WOUT) + c * WOUT + f] = fmaxf(o, 0.f);
    }
}

// ---------------------------------------------------------------------------
extern "C" void kernel_launch(void* const* d_in, const int* in_sizes, int n_in,
                              void* d_out, int out_size) {
    const float* A   = (const float*)d_in[0];
    const float* X   = (const float*)d_in[1];
    const float* W1a = (const float*)d_in[2];
    const float* W1b = (const float*)d_in[3];
    const float* Wg  = (const float*)d_in[4];
    const float* bg  = (const float*)d_in[5];
    float* out = (float*)d_out;

    k_phase1<<<NN + GEMM_BLOCKS, 256>>>(A, X, Wg, W1a, W1b);
    k_y<<<NN, 256>>>();
    k_final<<<NN, 256>>>(bg, out);
}

// round 3
// speedup vs baseline: 1.0110x; 1.0110x over previous
#include <cuda_runtime.h>

// ---------------------------------------------------------------------------
// GTN forward, sparse-aware, round 2.
//   Phase1 (one kernel, concurrent roles):
//     blocks [0,2048):   softmax weights (in-block) + sparsify A rows
//     blocks [2048,2304): XW = X @ Wg  (32x64 tiles)
//   k_y:    Y[c] = A2[c] @ XW   (unrolled-by-4 sparse gather)
//   k_final: dense smem H row via warp-parallel scatter, threshold/degree,
//            out = relu(coef * (A1 . Y - dropped corrections) + bg)
// ---------------------------------------------------------------------------

#define NN 2048
#define NE 4
#define NC 2
#define WIN 512
#define WOUT 256
#define CAP 128
#define MAXDROP 256
#define THRESH 0.05f
#define WEPS 1e-4f

#define GEMM_MT 32
#define GEMM_NT 64
#define GEMM_BLOCKS ((NN / GEMM_MT) * (WOUT / GEMM_NT))   // 64*4 = 256

// Scratch (device globals; no allocations allowed)
__device__ int   g_nnz[NN];
__device__ int   g_cols[NN * CAP];
__device__ float g_a1[NN * CAP * NC];   // [(row*CAP+slot)*2 + c]
__device__ float g_a2[NN * CAP * NC];
__device__ float g_XW[NN * WOUT];
__device__ float g_Y[NC][NN * WOUT];

// ---------------------------------------------------------------- phase 1
struct P1Smem {
    union {
        struct {
            float As[16][GEMM_MT];
            float Bs[16][GEMM_NT];
        } g;
        struct {
            int   cnt;
            float f1[NC][NE];
            float f2[NC][NE];
        } s;
    } u;
};

__global__ void k_phase1(const float* __restrict__ A,
                         const float* __restrict__ X,
                         const float* __restrict__ Wg,
                         const float* __restrict__ W1a,
                         const float* __restrict__ W1b) {
    __shared__ P1Smem sm;
    const int tid = threadIdx.x;

    if (blockIdx.x < NN) {
        // ------------------------------------------- sparsify role
        const int i = blockIdx.x;
        if (tid == 0) {
            sm.u.s.cnt = 0;
            // softmax over edge dim, threshold < 1e-4 -> 0 (redundant per
            // block, deterministic, trivially cheap)
            for (int c = 0; c < NC; c++) {
                float m = -1e30f;
                for (int e = 0; e < NE; e++) m = fmaxf(m, W1a[c * NE + e]);
                float ex[NE], s = 0.f;
                for (int e = 0; e < NE; e++) { ex[e] = expf(W1a[c * NE + e] - m); s += ex[e]; }
                for (int e = 0; e < NE; e++) {
                    float f = ex[e] / s;
                    sm.u.s.f1[c][e] = (f < WEPS) ? 0.f : f;
                }
                m = -1e30f;
                for (int e = 0; e < NE; e++) m = fmaxf(m, W1b[c * NE + e]);
                s = 0.f;
                for (int e = 0; e < NE; e++) { ex[e] = expf(W1b[c * NE + e] - m); s += ex[e]; }
                for (int e = 0; e < NE; e++) {
                    float f = ex[e] / s;
                    sm.u.s.f2[c][e] = (f < WEPS) ? 0.f : f;
                }
            }
        }
        __syncthreads();

        const size_t planeStride = (size_t)NN * NN;
        const float* base = A + (size_t)i * NN;

        #pragma unroll
        for (int g = 0; g < 2; g++) {
            int j0 = tid * 4 + g * 1024;
            float4 v[NE];
            #pragma unroll
            for (int e = 0; e < NE; e++)
                v[e] = *(const float4*)(base + (size_t)e * planeStride + j0);

            #pragma unroll
            for (int l = 0; l < 4; l++) {
                float a[NE];
                a[0] = l == 0 ? v[0].x : l == 1 ? v[0].y : l == 2 ? v[0].z : v[0].w;
                a[1] = l == 0 ? v[1].x : l == 1 ? v[1].y : l == 2 ? v[1].z : v[1].w;
                a[2] = l == 0 ? v[2].x : l == 1 ? v[2].y : l == 2 ? v[2].z : v[2].w;
                a[3] = l == 0 ? v[3].x : l == 1 ? v[3].y : l == 2 ? v[3].z : v[3].w;
                bool nz = (a[0] != 0.f) | (a[1] != 0.f) | (a[2] != 0.f) | (a[3] != 0.f);
                if (nz) {
                    int slot = atomicAdd(&sm.u.s.cnt, 1);
                    if (slot < CAP) {
                        int idx = i * CAP + slot;
                        g_cols[idx] = j0 + l;
                        #pragma unroll
                        for (int c = 0; c < NC; c++) {
                            g_a1[idx * 2 + c] =
                                sm.u.s.f1[c][0] * a[0] + sm.u.s.f1[c][1] * a[1] +
                                sm.u.s.f1[c][2] * a[2] + sm.u.s.f1[c][3] * a[3];
                            g_a2[idx * 2 + c] =
                                sm.u.s.f2[c][0] * a[0] + sm.u.s.f2[c][1] * a[1] +
                                sm.u.s.f2[c][2] * a[2] + sm.u.s.f2[c][3] * a[3];
                        }
                    }
                }
            }
        }
        __syncthreads();
        if (tid == 0) g_nnz[i] = min(sm.u.s.cnt, CAP);
    } else {
        // ------------------------------------------- GEMM role: XW = X @ Wg
        const int b  = blockIdx.x - NN;
        const int bm = (b >> 2) * GEMM_MT;       // 64 m-tiles
        const int bn = (b & 3) * GEMM_NT;        // 4 n-tiles
        const int tx = tid & 15;                 // n / 4
        const int ty = tid >> 4;                 // m / 2
        float acc[2][4] = {};

        for (int k0 = 0; k0 < WIN; k0 += 16) {
            #pragma unroll
            for (int t = 0; t < 2; t++) {
                int idx = tid + t * 256;
                int m = idx >> 4, kk = idx & 15;
                sm.u.g.As[kk][m] = X[(size_t)(bm + m) * WIN + k0 + kk];
            }
            #pragma unroll
            for (int t = 0; t < 4; t++) {
                int idx = tid + t * 256;
                int kk = idx >> 6, n = idx & 63;
                sm.u.g.Bs[kk][n] = Wg[(size_t)(k0 + kk) * WOUT + bn + n];
            }
            __syncthreads();
            #pragma unroll
            for (int k = 0; k < 16; k++) {
                float a0 = sm.u.g.As[k][ty * 2 + 0];
                float a1 = sm.u.g.As[k][ty * 2 + 1];
                float4 b4 = *(const float4*)&sm.u.g.Bs[k][tx * 4];
                acc[0][0] = fmaf(a0, b4.x, acc[0][0]);
                acc[0][1] = fmaf(a0, b4.y, acc[0][1]);
                acc[0][2] = fmaf(a0, b4.z, acc[0][2]);
                acc[0][3] = fmaf(a0, b4.w, acc[0][3]);
                acc[1][0] = fmaf(a1, b4.x, acc[1][0]);
                acc[1][1] = fmaf(a1, b4.y, acc[1][1]);
                acc[1][2] = fmaf(a1, b4.z, acc[1][2]);
                acc[1][3] = fmaf(a1, b4.w, acc[1][3]);
            }
            __syncthreads();
        }
        #pragma unroll
        for (int u = 0; u < 2; u++) {
            float4 o = make_float4(acc[u][0], acc[u][1], acc[u][2], acc[u][3]);
            *(float4*)&g_XW[(size_t)(bm + ty * 2 + u) * WOUT + bn + tx * 4] = o;
        }
    }
}

// ---------------------------------------------------------------- kernel y
// Y[c][k][:] = sum_s a2[c][k][s] * XW[col[s]][:]   (unroll-by-4 gather)
__global__ void k_y() {
    const int k = blockIdx.x;
    const int f = threadIdx.x;          // 256 threads = feature
    __shared__ int   scol[CAP];
    __shared__ float sv0[CAP], sv1[CAP];
    const int n2 = g_nnz[k];
    for (int s = f; s < n2; s += 256) {
        int idx = k * CAP + s;
        scol[s] = g_cols[idx] * WOUT;
        sv0[s] = g_a2[idx * 2 + 0];
        sv1[s] = g_a2[idx * 2 + 1];
    }
    __syncthreads();
    float acc0 = 0.f, acc1 = 0.f;
    int s = 0;
    for (; s + 4 <= n2; s += 4) {
        float x0 = g_XW[scol[s + 0] + f];
        float x1 = g_XW[scol[s + 1] + f];
        float x2 = g_XW[scol[s + 2] + f];
        float x3 = g_XW[scol[s + 3] + f];
        acc0 = fmaf(sv0[s + 0], x0, acc0);
        acc1 = fmaf(sv1[s + 0], x0, acc1);
        acc0 = fmaf(sv0[s + 1], x1, acc0);
        acc1 = fmaf(sv1[s + 1], x1, acc1);
        acc0 = fmaf(sv0[s + 2], x2, acc0);
        acc1 = fmaf(sv1[s + 2], x2, acc1);
        acc0 = fmaf(sv0[s + 3], x3, acc0);
        acc1 = fmaf(sv1[s + 3], x3, acc1);
    }
    for (; s < n2; s++) {
        float x = g_XW[scol[s] + f];
        acc0 = fmaf(sv0[s], x, acc0);
        acc1 = fmaf(sv1[s], x, acc1);
    }
    g_Y[0][(size_t)k * WOUT + f] = acc0;
    g_Y[1][(size_t)k * WOUT + f] = acc1;
}

// ---------------------------------------------------------------- kernel final
__global__ void k_final(const float* __restrict__ bg, float* __restrict__ out) {
    const int i = blockIdx.x;
    const int tid = threadIdx.x;        // 256
    const int warp = tid >> 5, lane = tid & 31;

    __shared__ float H0[NN], H1[NN];    // 16 KB dense row accumulators
    __shared__ int   c1s[CAP];
    __shared__ float w0s[CAP], w1s[CAP];
    __shared__ float degsh[NC];
    __shared__ int   dropn[NC];
    __shared__ int   dropj[NC][MAXDROP];
    __shared__ float droph[NC][MAXDROP];

    float4 z = make_float4(0.f, 0.f, 0.f, 0.f);
    for (int t = tid; t < NN / 4; t += 256) {
        ((float4*)H0)[t] = z;
        ((float4*)H1)[t] = z;
    }
    if (tid < NC) { degsh[tid] = 0.f; dropn[tid] = 0; }
    const int n1 = g_nnz[i];
    for (int s = tid; s < n1; s += 256) {
        int idx = i * CAP + s;
        c1s[s] = g_cols[idx];
        w0s[s] = g_a1[idx * 2 + 0];
        w1s[s] = g_a1[idx * 2 + 1];
    }
    __syncthreads();

    // scatter: one warp per source slot s, lanes over target slots s2
    for (int s = warp; s < n1; s += 8) {
        int k = c1s[s];
        int n2 = g_nnz[k];
        float w0 = w0s[s], w1 = w1s[s];
        for (int s2 = lane; s2 < n2; s2 += 32) {
            int idx = k * CAP + s2;
            int j = g_cols[idx];
            float h0 = w0 * g_a2[idx * 2 + 0];
            float h1 = w1 * g_a2[idx * 2 + 1];
            if (h0 != 0.f) atomicAdd(&H0[j], h0);
            if (h1 != 0.f) atomicAdd(&H1[j], h1);
        }
    }
    __syncthreads();

    // threshold scan: degree sums + dropped-entry lists
    float d0 = 0.f, d1 = 0.f;
    for (int j = tid; j < NN; j += 256) {
        float h0 = H0[j];
        if (h0 > THRESH) d0 += h0;
        else if (h0 > 0.f) {
            int p = atomicAdd(&dropn[0], 1);
            if (p < MAXDROP) { dropj[0][p] = j; droph[0][p] = h0; }
        }
        float h1 = H1[j];
        if (h1 > THRESH) d1 += h1;
        else if (h1 > 0.f) {
            int p = atomicAdd(&dropn[1], 1);
            if (p < MAXDROP) { dropj[1][p] = j; droph[1][p] = h1; }
        }
    }
    #pragma unroll
    for (int o = 16; o > 0; o >>= 1) {
        d0 += __shfl_down_sync(0xffffffff, d0, o);
        d1 += __shfl_down_sync(0xffffffff, d1, o);
    }
    if (lane == 0) {
        if (d0 != 0.f) atomicAdd(&degsh[0], d0);
        if (d1 != 0.f) atomicAdd(&degsh[1], d1);
    }
    __syncthreads();

    float coef[NC];
    #pragma unroll
    for (int c = 0; c < NC; c++) {
        float deg = degsh[c];
        if (deg > 0.f) {
            float dinv = 1.f / deg;
            float deg2 = deg * dinv;      // double row-normalization
            coef[c] = dinv * (1.f / deg2);
        } else {
            coef[c] = 0.f;
        }
    }

    // output: feature f = tid, unroll-by-4 sparse gather of Y rows
    const int f = tid;
    const float bias = bg[f];
    #pragma unroll
    for (int c = 0; c < NC; c++) {
        const float* Yc = g_Y[c];
        const float* ws = (c == 0) ? w0s : w1s;
        float acc = 0.f;
        int s = 0;
        for (; s + 4 <= n1; s += 4) {
            float y0 = Yc[(size_t)c1s[s + 0] * WOUT + f];
            float y1 = Yc[(size_t)c1s[s + 1] * WOUT + f];
            float y2 = Yc[(size_t)c1s[s + 2] * WOUT + f];
            float y3 = Yc[(size_t)c1s[s + 3] * WOUT + f];
            acc = fmaf(ws[s + 0], y0, acc);
            acc = fmaf(ws[s + 1], y1, acc);
            acc = fmaf(ws[s + 2], y2, acc);
            acc = fmaf(ws[s + 3], y3, acc);
        }
        for (; s < n1; s++)
            acc = fmaf(ws[s], Yc[(size_t)c1s[s] * WOUT + f], acc);

        int nd = min(dropn[c], MAXDROP);
        for (int d = 0; d < nd; d++)
            acc -= droph[c][d] * g_XW[(size_t)dropj[c][d] * WOUT + f];

        float o = coef[c] * acc + bias;
        out[(size_t)i * (NC * WOUT) + c * WOUT + f] = fmaxf(o, 0.f);
    }
}

// ---------------------------------------------------------------------------
extern "C" void kernel_launch(void* const* d_in, const int* in_sizes, int n_in,
                              void* d_out, int out_size) {
    const float* A   = (const float*)d_in[0];
    const float* X   = (const float*)d_in[1];
    const float* W1a = (const float*)d_in[2];
    const float* W1b = (const float*)d_in[3];
    const float* Wg  = (const float*)d_in[4];
    const float* bg  = (const float*)d_in[5];
    float* out = (float*)d_out;

    k_phase1<<<NN + GEMM_BLOCKS, 256>>>(A, X, Wg, W1a, W1b);
    k_y<<<NN, 256>>>();
    k_final<<<NN, 256>>>(bg, out);
}

// round 4
// speedup vs baseline: 1.0900x; 1.0782x over previous
#include <cuda_runtime.h>

// ---------------------------------------------------------------------------
// GTN forward, sparse-aware, round 3.
//   k_weights: softmax edge weights f1,f2 (tiny)
//   k_phase1 (fused, gemm-first ordering):
//     blocks [0,128):     XW = X @ Wg  (64x64 tiles, 512 thr)
//     blocks [128,2176):  sparsify A rows (512 thr, 4 independent plane loads)
//   k_y:     Y[c] = A2[c] @ XW  (unroll-4 sparse gather)
//   k_final: dense smem H row (warp-parallel scatter), threshold/degree,
//            out = relu(coef * (A1 . Y - dropped corrections) + bg)
// ---------------------------------------------------------------------------

#define NN 2048
#define NE 4
#define NC 2
#define WIN 512
#define WOUT 256
#define CAP 128
#define MAXDROP 256
#define THRESH 0.05f
#define WEPS 1e-4f
#define GEMM_BLOCKS 128      // (2048/64) * (256/64)

// Scratch (device globals; no allocations allowed)
__device__ float  g_f1[NC][NE];
__device__ float  g_f2[NC][NE];
__device__ int    g_nnz[NN];
__device__ int    g_cols[NN * CAP];
__device__ float2 g_a1[NN * CAP];       // (.x,.y) = channel 0,1
__device__ float2 g_a2[NN * CAP];
__device__ float  g_XW[NN * WOUT];
__device__ float  g_Y[NC][NN * WOUT];

// ---------------------------------------------------------------- weights
__global__ void k_weights(const float* __restrict__ W1a,
                          const float* __restrict__ W1b) {
    if (threadIdx.x == 0) {
        for (int c = 0; c < NC; c++) {
            float m = -1e30f;
            for (int e = 0; e < NE; e++) m = fmaxf(m, W1a[c * NE + e]);
            float ex[NE], s = 0.f;
            for (int e = 0; e < NE; e++) { ex[e] = expf(W1a[c * NE + e] - m); s += ex[e]; }
            for (int e = 0; e < NE; e++) {
                float f = ex[e] / s;
                g_f1[c][e] = (f < WEPS) ? 0.f : f;
            }
            m = -1e30f;
            for (int e = 0; e < NE; e++) m = fmaxf(m, W1b[c * NE + e]);
            s = 0.f;
            for (int e = 0; e < NE; e++) { ex[e] = expf(W1b[c * NE + e] - m); s += ex[e]; }
            for (int e = 0; e < NE; e++) {
                float f = ex[e] / s;
                g_f2[c][e] = (f < WEPS) ? 0.f : f;
            }
        }
    }
}

// ---------------------------------------------------------------- phase 1
__global__ void __launch_bounds__(512, 3)
k_phase1(const float* __restrict__ A,
         const float* __restrict__ X,
         const float* __restrict__ Wg) {
    __shared__ float As[16][64];
    __shared__ float Bs[16][64];
    __shared__ int   cnt;
    __shared__ float f1s[NC][NE], f2s[NC][NE];
    const int tid = threadIdx.x;

    if (blockIdx.x >= GEMM_BLOCKS) {
        // ------------------------------------------- sparsify role
        const int i = blockIdx.x - GEMM_BLOCKS;
        if (tid == 0) cnt = 0;
        if (tid < NC * NE) {
            int c = tid / NE, e = tid % NE;
            f1s[c][e] = g_f1[c][e];
            f2s[c][e] = g_f2[c][e];
        }
        __syncthreads();

        const size_t PS = (size_t)NN * NN;
        const float* base = A + (size_t)i * NN + tid * 4;
        // 4 independent plane loads, one batch
        float4 v0 = __ldg((const float4*)(base));
        float4 v1 = __ldg((const float4*)(base + PS));
        float4 v2 = __ldg((const float4*)(base + 2 * PS));
        float4 v3 = __ldg((const float4*)(base + 3 * PS));

        #pragma unroll
        for (int l = 0; l < 4; l++) {
            float a0 = l == 0 ? v0.x : l == 1 ? v0.y : l == 2 ? v0.z : v0.w;
            float a1 = l == 0 ? v1.x : l == 1 ? v1.y : l == 2 ? v1.z : v1.w;
            float a2 = l == 0 ? v2.x : l == 1 ? v2.y : l == 2 ? v2.z : v2.w;
            float a3 = l == 0 ? v3.x : l == 1 ? v3.y : l == 2 ? v3.z : v3.w;
            bool nz = (a0 != 0.f) | (a1 != 0.f) | (a2 != 0.f) | (a3 != 0.f);
            if (nz) {
                int slot = atomicAdd(&cnt, 1);
                if (slot < CAP) {
                    int idx = i * CAP + slot;
                    g_cols[idx] = tid * 4 + l;
                    g_a1[idx] = make_float2(
                        f1s[0][0] * a0 + f1s[0][1] * a1 + f1s[0][2] * a2 + f1s[0][3] * a3,
                        f1s[1][0] * a0 + f1s[1][1] * a1 + f1s[1][2] * a2 + f1s[1][3] * a3);
                    g_a2[idx] = make_float2(
                        f2s[0][0] * a0 + f2s[0][1] * a1 + f2s[0][2] * a2 + f2s[0][3] * a3,
                        f2s[1][0] * a0 + f2s[1][1] * a1 + f2s[1][2] * a2 + f2s[1][3] * a3);
                }
            }
        }
        __syncthreads();
        if (tid == 0) g_nnz[i] = min(cnt, CAP);
    } else {
        // ------------------------------------------- GEMM role: XW = X @ Wg
        const int b  = blockIdx.x;
        const int bm = (b >> 2) * 64;            // 32 m-tiles
        const int bn = (b & 3) * 64;             // 4 n-tiles
        const int tx = tid & 15;                 // n / 4
        const int ty = tid >> 4;                 // m / 2  (0..31)
        float acc[2][4] = {};

        for (int k0 = 0; k0 < WIN; k0 += 16) {
            #pragma unroll
            for (int t = 0; t < 2; t++) {
                int idx = tid + t * 512;
                int m = idx >> 4, kk = idx & 15;
                As[kk][m] = X[(size_t)(bm + m) * WIN + k0 + kk];
            }
            #pragma unroll
            for (int t = 0; t < 2; t++) {
                int idx = tid + t * 512;
                int kk = idx >> 6, n = idx & 63;
                Bs[kk][n] = Wg[(size_t)(k0 + kk) * WOUT + bn + n];
            }
            __syncthreads();
            #pragma unroll
            for (int k = 0; k < 16; k++) {
                float a0 = As[k][ty * 2 + 0];
                float a1 = As[k][ty * 2 + 1];
                float4 b4 = *(const float4*)&Bs[k][tx * 4];
                acc[0][0] = fmaf(a0, b4.x, acc[0][0]);
                acc[0][1] = fmaf(a0, b4.y, acc[0][1]);
                acc[0][2] = fmaf(a0, b4.z, acc[0][2]);
                acc[0][3] = fmaf(a0, b4.w, acc[0][3]);
                acc[1][0] = fmaf(a1, b4.x, acc[1][0]);
                acc[1][1] = fmaf(a1, b4.y, acc[1][1]);
                acc[1][2] = fmaf(a1, b4.z, acc[1][2]);
                acc[1][3] = fmaf(a1, b4.w, acc[1][3]);
            }
            __syncthreads();
        }
        #pragma unroll
        for (int u = 0; u < 2; u++) {
            float4 o = make_float4(acc[u][0], acc[u][1], acc[u][2], acc[u][3]);
            *(float4*)&g_XW[(size_t)(bm + ty * 2 + u) * WOUT + bn + tx * 4] = o;
        }
    }
}

// ---------------------------------------------------------------- kernel y
// Y[c][k][:] = sum_s a2[c][k][s] * XW[col[s]][:]   (unroll-by-4 gather)
__global__ void k_y() {
    const int k = blockIdx.x;
    const int f = threadIdx.x;          // 256 threads = feature
    __shared__ int   scol[CAP];
    __shared__ float sv0[CAP], sv1[CAP];
    const int n2 = g_nnz[k];
    for (int s = f; s < n2; s += 256) {
        int idx = k * CAP + s;
        scol[s] = g_cols[idx] * WOUT;
        float2 a = g_a2[idx];
        sv0[s] = a.x;
        sv1[s] = a.y;
    }
    __syncthreads();
    float acc0 = 0.f, acc1 = 0.f;
    int s = 0;
    for (; s + 4 <= n2; s += 4) {
        float x0 = g_XW[scol[s + 0] + f];
        float x1 = g_XW[scol[s + 1] + f];
        float x2 = g_XW[scol[s + 2] + f];
        float x3 = g_XW[scol[s + 3] + f];
        acc0 = fmaf(sv0[s + 0], x0, acc0);
        acc1 = fmaf(sv1[s + 0], x0, acc1);
        acc0 = fmaf(sv0[s + 1], x1, acc0);
        acc1 = fmaf(sv1[s + 1], x1, acc1);
        acc0 = fmaf(sv0[s + 2], x2, acc0);
        acc1 = fmaf(sv1[s + 2], x2, acc1);
        acc0 = fmaf(sv0[s + 3], x3, acc0);
        acc1 = fmaf(sv1[s + 3], x3, acc1);
    }
    for (; s < n2; s++) {
        float x = g_XW[scol[s] + f];
        acc0 = fmaf(sv0[s], x, acc0);
        acc1 = fmaf(sv1[s], x, acc1);
    }
    g_Y[0][(size_t)k * WOUT + f] = acc0;
    g_Y[1][(size_t)k * WOUT + f] = acc1;
}

// ---------------------------------------------------------------- kernel final
__global__ void k_final(const float* __restrict__ bg, float* __restrict__ out) {
    const int i = blockIdx.x;
    const int tid = threadIdx.x;        // 256
    const int warp = tid >> 5, lane = tid & 31;

    __shared__ float H0[NN], H1[NN];    // 16 KB dense row accumulators
    __shared__ int   c1s[CAP];
    __shared__ float w0s[CAP], w1s[CAP];
    __shared__ float degsh[NC];
    __shared__ int   dropn[NC];
    __shared__ int   dropj[NC][MAXDROP];
    __shared__ float droph[NC][MAXDROP];

    float4 z = make_float4(0.f, 0.f, 0.f, 0.f);
    for (int t = tid; t < NN / 4; t += 256) {
        ((float4*)H0)[t] = z;
        ((float4*)H1)[t] = z;
    }
    if (tid < NC) { degsh[tid] = 0.f; dropn[tid] = 0; }
    const int n1 = g_nnz[i];
    for (int s = tid; s < n1; s += 256) {
        int idx = i * CAP + s;
        c1s[s] = g_cols[idx];
        float2 a = g_a1[idx];
        w0s[s] = a.x;
        w1s[s] = a.y;
    }
    __syncthreads();

    // scatter: one warp per source slot s, lanes over target slots s2
    for (int s = warp; s < n1; s += 8) {
        int k = c1s[s];
        int n2 = g_nnz[k];
        float w0 = w0s[s], w1 = w1s[s];
        for (int s2 = lane; s2 < n2; s2 += 32) {
            int idx = k * CAP + s2;
            int j = g_cols[idx];
            float2 a = g_a2[idx];
            float h0 = w0 * a.x;
            float h1 = w1 * a.y;
            if (h0 != 0.f) atomicAdd(&H0[j], h0);
            if (h1 != 0.f) atomicAdd(&H1[j], h1);
        }
    }
    __syncthreads();

    // threshold scan: degree sums + dropped-entry lists
    float d0 = 0.f, d1 = 0.f;
    for (int j = tid; j < NN; j += 256) {
        float h0 = H0[j];
        if (h0 > THRESH) d0 += h0;
        else if (h0 > 0.f) {
            int p = atomicAdd(&dropn[0], 1);
            if (p < MAXDROP) { dropj[0][p] = j; droph[0][p] = h0; }
        }
        float h1 = H1[j];
        if (h1 > THRESH) d1 += h1;
        else if (h1 > 0.f) {
            int p = atomicAdd(&dropn[1], 1);
            if (p < MAXDROP) { dropj[1][p] = j; droph[1][p] = h1; }
        }
    }
    #pragma unroll
    for (int o = 16; o > 0; o >>= 1) {
        d0 += __shfl_down_sync(0xffffffff, d0, o);
        d1 += __shfl_down_sync(0xffffffff, d1, o);
    }
    if (lane == 0) {
        if (d0 != 0.f) atomicAdd(&degsh[0], d0);
        if (d1 != 0.f) atomicAdd(&degsh[1], d1);
    }
    __syncthreads();

    float coef[NC];
    #pragma unroll
    for (int c = 0; c < NC; c++) {
        float deg = degsh[c];
        if (deg > 0.f) {
            float dinv = 1.f / deg;
            float deg2 = deg * dinv;      // double row-normalization
            coef[c] = dinv * (1.f / deg2);
        } else {
            coef[c] = 0.f;
        }
    }

    // output: feature f = tid, unroll-by-4 sparse gather of Y rows
    const int f = tid;
    const float bias = bg[f];
    #pragma unroll
    for (int c = 0; c < NC; c++) {
        const float* Yc = g_Y[c];
        const float* ws = (c == 0) ? w0s : w1s;
        float acc = 0.f;
        int s = 0;
        for (; s + 4 <= n1; s += 4) {
            float y0 = Yc[(size_t)c1s[s + 0] * WOUT + f];
            float y1 = Yc[(size_t)c1s[s + 1] * WOUT + f];
            float y2 = Yc[(size_t)c1s[s + 2] * WOUT + f];
            float y3 = Yc[(size_t)c1s[s + 3] * WOUT + f];
            acc = fmaf(ws[s + 0], y0, acc);
            acc = fmaf(ws[s + 1], y1, acc);
            acc = fmaf(ws[s + 2], y2, acc);
            acc = fmaf(ws[s + 3], y3, acc);
        }
        for (; s < n1; s++)
            acc = fmaf(ws[s], Yc[(size_t)c1s[s] * WOUT + f], acc);

        int nd = min(dropn[c], MAXDROP);
        for (int d = 0; d < nd; d++)
            acc -= droph[c][d] * g_XW[(size_t)dropj[c][d] * WOUT + f];

        float o = coef[c] * acc + bias;
        out[(size_t)i * (NC * WOUT) + c * WOUT + f] = fmaxf(o, 0.f);
    }
}

// ---------------------------------------------------------------------------
extern "C" void kernel_launch(void* const* d_in, const int* in_sizes, int n_in,
                              void* d_out, int out_size) {
    const float* A   = (const float*)d_in[0];
    const float* X   = (const float*)d_in[1];
    const float* W1a = (const float*)d_in[2];
    const float* W1b = (const float*)d_in[3];
    const float* Wg  = (const float*)d_in[4];
    const float* bg  = (const float*)d_in[5];
    float* out = (float*)d_out;

    k_weights<<<1, 32>>>(W1a, W1b);
    k_phase1<<<GEMM_BLOCKS + NN, 512>>>(A, X, Wg);
    k_y<<<NN, 256>>>();
    k_final<<<NN, 256>>>(bg, out);
}

// round 5
// speedup vs baseline: 1.2791x; 1.1734x over previous
#include <cuda_runtime.h>

// ---------------------------------------------------------------------------
// GTN forward, round 4.
//   k_pre  : blocks [0,256): XW = X @ Wg (32x64 tiles)
//            blocks [256,264): zero g_nnz + softmax edge weights
//   k_scan : pure streaming sparsify of A — flat float4 grid, 8 independent
//            loads/thread, global-atomic slot assignment, no smem/barriers
//   k_y    : Y[c] = A2[c] @ XW (unroll-8 sparse gather)
//   k_final: dense smem H row (warp scatter w/ prefetched nnz), threshold,
//            out = relu(coef * (A1 . Y - dropped corrections) + bg)
// ---------------------------------------------------------------------------

#define NN 2048
#define NE 4
#define NC 2
#define WIN 512
#define WOUT 256
#define CAP 128
#define MAXDROP 128
#define THRESH 0.05f
#define WEPS 1e-4f

#define PLANE4 ((size_t)NN * NN / 4)    // float4 per plane = 1048576
#define HALF4  (PLANE4 / 2)             // 524288
#define SCAN_BLOCKS 2048                // 2048*256 = HALF4 threads
#define GEMM_BLOCKS 256                 // (2048/32)*(256/64)

// Scratch (device globals; no allocations allowed)
__device__ float4 g_f1v[NC];            // softmaxed edge weights, channel-major
__device__ float4 g_f2v[NC];
__device__ int    g_nnz[NN];
__device__ int    g_cols[NN * CAP];
__device__ float2 g_a1[NN * CAP];       // (.x,.y) = channel 0,1
__device__ float2 g_a2[NN * CAP];
__device__ float  g_XW[NN * WOUT];
__device__ float  g_Y[NC][NN * WOUT];

// ---------------------------------------------------------------- k_pre
__global__ void __launch_bounds__(256) k_pre(const float* __restrict__ X,
                                             const float* __restrict__ Wg,
                                             const float* __restrict__ W1a,
                                             const float* __restrict__ W1b) {
    __shared__ float As[16][32];
    __shared__ float Bs[16][64];
    const int tid = threadIdx.x;

    if (blockIdx.x >= GEMM_BLOCKS) {
        // ---------------------------------- init role: zero nnz + softmax
        int t = (blockIdx.x - GEMM_BLOCKS) * 256 + tid;
        if (t < NN) g_nnz[t] = 0;
        if (blockIdx.x == GEMM_BLOCKS && tid == 0) {
            for (int c = 0; c < NC; c++) {
                float m = -1e30f;
                for (int e = 0; e < NE; e++) m = fmaxf(m, W1a[c * NE + e]);
                float ex[NE], s = 0.f;
                for (int e = 0; e < NE; e++) { ex[e] = expf(W1a[c * NE + e] - m); s += ex[e]; }
                float f[NE];
                for (int e = 0; e < NE; e++) {
                    float w = ex[e] / s;
                    f[e] = (w < WEPS) ? 0.f : w;
                }
                g_f1v[c] = make_float4(f[0], f[1], f[2], f[3]);

                m = -1e30f;
                for (int e = 0; e < NE; e++) m = fmaxf(m, W1b[c * NE + e]);
                s = 0.f;
                for (int e = 0; e < NE; e++) { ex[e] = expf(W1b[c * NE + e] - m); s += ex[e]; }
                for (int e = 0; e < NE; e++) {
                    float w = ex[e] / s;
                    f[e] = (w < WEPS) ? 0.f : w;
                }
                g_f2v[c] = make_float4(f[0], f[1], f[2], f[3]);
            }
        }
        return;
    }

    // -------------------------------------- GEMM role: XW = X @ Wg
    const int b  = blockIdx.x;
    const int bm = (b >> 2) * 32;
    const int bn = (b & 3) * 64;
    const int tx = tid & 15;            // n / 4
    const int ty = tid >> 4;            // 0..15, 2 m-rows each
    float acc[2][4] = {};

    for (int k0 = 0; k0 < WIN; k0 += 16) {
        #pragma unroll
        for (int t = 0; t < 2; t++) {
            int idx = tid + t * 256;
            int m = idx & 31, kk = idx >> 5;
            As[kk][m] = X[(size_t)(bm + m) * WIN + k0 + kk];
        }
        #pragma unroll
        for (int t = 0; t < 4; t++) {
            int idx = tid + t * 256;
            int n = idx & 63, kk = idx >> 6;
            Bs[kk][n] = Wg[(size_t)(k0 + kk) * WOUT + bn + n];
        }
        __syncthreads();
        #pragma unroll
        for (int k = 0; k < 16; k++) {
            float a0 = As[k][ty * 2 + 0];
            float a1 = As[k][ty * 2 + 1];
            float4 b4 = *(const float4*)&Bs[k][tx * 4];
            acc[0][0] = fmaf(a0, b4.x, acc[0][0]);
            acc[0][1] = fmaf(a0, b4.y, acc[0][1]);
            acc[0][2] = fmaf(a0, b4.z, acc[0][2]);
            acc[0][3] = fmaf(a0, b4.w, acc[0][3]);
            acc[1][0] = fmaf(a1, b4.x, acc[1][0]);
            acc[1][1] = fmaf(a1, b4.y, acc[1][1]);
            acc[1][2] = fmaf(a1, b4.z, acc[1][2]);
            acc[1][3] = fmaf(a1, b4.w, acc[1][3]);
        }
        __syncthreads();
    }
    #pragma unroll
    for (int u = 0; u < 2; u++) {
        float4 o = make_float4(acc[u][0], acc[u][1], acc[u][2], acc[u][3]);
        *(float4*)&g_XW[(size_t)(bm + ty * 2 + u) * WOUT + bn + tx * 4] = o;
    }
}

// ---------------------------------------------------------------- k_scan
__device__ __forceinline__ void scan_emit(int i, int j0, int l,
                                          float a0, float a1, float a2, float a3,
                                          const float4& f1a, const float4& f1b,
                                          const float4& f2a, const float4& f2b) {
    bool nz = (a0 != 0.f) | (a1 != 0.f) | (a2 != 0.f) | (a3 != 0.f);
    if (nz) {
        int slot = atomicAdd(&g_nnz[i], 1);
        if (slot < CAP) {
            int idx = i * CAP + slot;
            g_cols[idx] = j0 + l;
            g_a1[idx] = make_float2(
                f1a.x * a0 + f1a.y * a1 + f1a.z * a2 + f1a.w * a3,
                f1b.x * a0 + f1b.y * a1 + f1b.z * a2 + f1b.w * a3);
            g_a2[idx] = make_float2(
                f2a.x * a0 + f2a.y * a1 + f2a.z * a2 + f2a.w * a3,
                f2b.x * a0 + f2b.y * a1 + f2b.z * a2 + f2b.w * a3);
        }
    }
}

__device__ __forceinline__ void scan_quad(size_t p,
                                          const float4& v0, const float4& v1,
                                          const float4& v2, const float4& v3,
                                          const float4& f1a, const float4& f1b,
                                          const float4& f2a, const float4& f2b) {
    int i = (int)(p >> 9);              // 512 float4 per row
    int j0 = ((int)p & 511) * 4;
    scan_emit(i, j0, 0, v0.x, v1.x, v2.x, v3.x, f1a, f1b, f2a, f2b);
    scan_emit(i, j0, 1, v0.y, v1.y, v2.y, v3.y, f1a, f1b, f2a, f2b);
    scan_emit(i, j0, 2, v0.z, v1.z, v2.z, v3.z, f1a, f1b, f2a, f2b);
    scan_emit(i, j0, 3, v0.w, v1.w, v2.w, v3.w, f1a, f1b, f2a, f2b);
}

__global__ void __launch_bounds__(256) k_scan(const float* __restrict__ A) {
    const size_t t = (size_t)blockIdx.x * 256 + threadIdx.x;   // 0..HALF4-1
    const float4* base = (const float4*)A;

    const float4 f1a = g_f1v[0], f1b = g_f1v[1];
    const float4 f2a = g_f2v[0], f2b = g_f2v[1];

    const size_t p0 = t;
    const size_t p1 = t + HALF4;

    // 8 fully independent loads in one batch
    float4 u0 = __ldg(base + p0);
    float4 u1 = __ldg(base + p0 + PLANE4);
    float4 u2 = __ldg(base + p0 + 2 * PLANE4);
    float4 u3 = __ldg(base + p0 + 3 * PLANE4);
    float4 w0 = __ldg(base + p1);
    float4 w1 = __ldg(base + p1 + PLANE4);
    float4 w2 = __ldg(base + p1 + 2 * PLANE4);
    float4 w3 = __ldg(base + p1 + 3 * PLANE4);

    scan_quad(p0, u0, u1, u2, u3, f1a, f1b, f2a, f2b);
    scan_quad(p1, w0, w1, w2, w3, f1a, f1b, f2a, f2b);
}

// ---------------------------------------------------------------- k_y
__global__ void __launch_bounds__(256) k_y() {
    const int k = blockIdx.x;
    const int f = threadIdx.x;
    __shared__ int   scol[CAP];
    __shared__ float sv0[CAP], sv1[CAP];
    const int n2 = min(g_nnz[k], CAP);
    for (int s = f; s < n2; s += 256) {
        int idx = k * CAP + s;
        scol[s] = g_cols[idx] * WOUT;
        float2 a = g_a2[idx];
        sv0[s] = a.x;
        sv1[s] = a.y;
    }
    __syncthreads();
    float acc0 = 0.f, acc1 = 0.f;
    int s = 0;
    for (; s + 8 <= n2; s += 8) {
        float x[8];
        #pragma unroll
        for (int u = 0; u < 8; u++) x[u] = __ldg(&g_XW[scol[s + u] + f]);
        #pragma unroll
        for (int u = 0; u < 8; u++) {
            acc0 = fmaf(sv0[s + u], x[u], acc0);
            acc1 = fmaf(sv1[s + u], x[u], acc1);
        }
    }
    for (; s + 4 <= n2; s += 4) {
        float x[4];
        #pragma unroll
        for (int u = 0; u < 4; u++) x[u] = __ldg(&g_XW[scol[s + u] + f]);
        #pragma unroll
        for (int u = 0; u < 4; u++) {
            acc0 = fmaf(sv0[s + u], x[u], acc0);
            acc1 = fmaf(sv1[s + u], x[u], acc1);
        }
    }
    for (; s < n2; s++) {
        float x = __ldg(&g_XW[scol[s] + f]);
        acc0 = fmaf(sv0[s], x, acc0);
        acc1 = fmaf(sv1[s], x, acc1);
    }
    g_Y[0][(size_t)k * WOUT + f] = acc0;
    g_Y[1][(size_t)k * WOUT + f] = acc1;
}

// ---------------------------------------------------------------- k_final
__global__ void __launch_bounds__(256) k_final(const float* __restrict__ bg,
                                               float* __restrict__ out) {
    const int i = blockIdx.x;
    const int tid = threadIdx.x;
    const int warp = tid >> 5, lane = tid & 31;

    __shared__ float H0[NN], H1[NN];
    __shared__ int   offs[CAP];          // c1*WOUT
    __shared__ int   n2s[CAP];           // prefetched neighbor nnz
    __shared__ float w0s[CAP], w1s[CAP];
    __shared__ float degsh[NC];
    __shared__ int   dropn[NC];
    __shared__ int   dropj[NC][MAXDROP];
    __shared__ float droph[NC][MAXDROP];

    float4 z = make_float4(0.f, 0.f, 0.f, 0.f);
    for (int t = tid; t < NN / 4; t += 256) {
        ((float4*)H0)[t] = z;
        ((float4*)H1)[t] = z;
    }
    if (tid < NC) { degsh[tid] = 0.f; dropn[tid] = 0; }
    const int n1 = min(g_nnz[i], CAP);
    for (int s = tid; s < n1; s += 256) {
        int idx = i * CAP + s;
        int c = g_cols[idx];
        offs[s] = c * WOUT;
        n2s[s] = min(g_nnz[c], CAP);     // prefetch neighbor nnz (batched)
        float2 a = g_a1[idx];
        w0s[s] = a.x;
        w1s[s] = a.y;
    }
    __syncthreads();

    // scatter: one warp per source slot s, lanes over target slots s2
    for (int s = warp; s < n1; s += 8) {
        int kbase = (offs[s] / WOUT) * CAP;
        int n2 = n2s[s];
        float w0 = w0s[s], w1 = w1s[s];
        for (int s2 = lane; s2 < n2; s2 += 32) {
            int idx = kbase + s2;
            int j = g_cols[idx];
            float2 a = g_a2[idx];
            float h0 = w0 * a.x;
            float h1 = w1 * a.y;
            if (h0 != 0.f) atomicAdd(&H0[j], h0);
            if (h1 != 0.f) atomicAdd(&H1[j], h1);
        }
    }
    __syncthreads();

    // threshold scan: degree sums + dropped-entry lists
    float d0 = 0.f, d1 = 0.f;
    for (int j = tid; j < NN; j += 256) {
        float h0 = H0[j];
        if (h0 > THRESH) d0 += h0;
        else if (h0 > 0.f) {
            int p = atomicAdd(&dropn[0], 1);
            if (p < MAXDROP) { dropj[0][p] = j; droph[0][p] = h0; }
        }
        float h1 = H1[j];
        if (h1 > THRESH) d1 += h1;
        else if (h1 > 0.f) {
            int p = atomicAdd(&dropn[1], 1);
            if (p < MAXDROP) { dropj[1][p] = j; droph[1][p] = h1; }
        }
    }
    #pragma unroll
    for (int o = 16; o > 0; o >>= 1) {
        d0 += __shfl_down_sync(0xffffffff, d0, o);
        d1 += __shfl_down_sync(0xffffffff, d1, o);
    }
    if (lane == 0) {
        if (d0 != 0.f) atomicAdd(&degsh[0], d0);
        if (d1 != 0.f) atomicAdd(&degsh[1], d1);
    }
    __syncthreads();

    float coef[NC];
    #pragma unroll
    for (int c = 0; c < NC; c++) {
        float deg = degsh[c];
        if (deg > 0.f) {
            float dinv = 1.f / deg;
            float deg2 = deg * dinv;     // double row-normalization
            coef[c] = dinv * (1.f / deg2);
        } else {
            coef[c] = 0.f;
        }
    }

    // output: feature f = tid; interleave channel gathers (8 loads in flight)
    const int f = tid;
    const float bias = bg[f];
    const float* Y0 = g_Y[0];
    const float* Y1 = g_Y[1];
    float acc0 = 0.f, acc1 = 0.f;
    int s = 0;
    for (; s + 4 <= n1; s += 4) {
        int o0 = offs[s + 0] + f, o1 = offs[s + 1] + f;
        int o2 = offs[s + 2] + f, o3 = offs[s + 3] + f;
        float a0 = __ldg(Y0 + o0), b0 = __ldg(Y1 + o0);
        float a1 = __ldg(Y0 + o1), b1 = __ldg(Y1 + o1);
        float a2 = __ldg(Y0 + o2), b2 = __ldg(Y1 + o2);
        float a3 = __ldg(Y0 + o3), b3 = __ldg(Y1 + o3);
        acc0 = fmaf(w0s[s + 0], a0, acc0); acc1 = fmaf(w1s[s + 0], b0, acc1);
        acc0 = fmaf(w0s[s + 1], a1, acc0); acc1 = fmaf(w1s[s + 1], b1, acc1);
        acc0 = fmaf(w0s[s + 2], a2, acc0); acc1 = fmaf(w1s[s + 2], b2, acc1);
        acc0 = fmaf(w0s[s + 3], a3, acc0); acc1 = fmaf(w1s[s + 3], b3, acc1);
    }
    for (; s < n1; s++) {
        int o = offs[s] + f;
        acc0 = fmaf(w0s[s], __ldg(Y0 + o), acc0);
        acc1 = fmaf(w1s[s], __ldg(Y1 + o), acc1);
    }

    int nd0 = min(dropn[0], MAXDROP);
    for (int d = 0; d < nd0; d++)
        acc0 -= droph[0][d] * g_XW[(size_t)dropj[0][d] * WOUT + f];
    int nd1 = min(dropn[1], MAXDROP);
    for (int d = 0; d < nd1; d++)
        acc1 -= droph[1][d] * g_XW[(size_t)dropj[1][d] * WOUT + f];

    float o0 = coef[0] * acc0 + bias;
    float o1 = coef[1] * acc1 + bias;
    out[(size_t)i * (NC * WOUT) + f]        = fmaxf(o0, 0.f);
    out[(size_t)i * (NC * WOUT) + WOUT + f] = fmaxf(o1, 0.f);
}

// ---------------------------------------------------------------------------
extern "C" void kernel_launch(void* const* d_in, const int* in_sizes, int n_in,
                              void* d_out, int out_size) {
    const float* A   = (const float*)d_in[0];
    const float* X   = (const float*)d_in[1];
    const float* W1a = (const float*)d_in[2];
    const float* W1b = (const float*)d_in[3];
    const float* Wg  = (const float*)d_in[4];
    const float* bg  = (const float*)d_in[5];
    float* out = (float*)d_out;

    k_pre<<<GEMM_BLOCKS + 8, 256>>>(X, Wg, W1a, W1b);
    k_scan<<<SCAN_BLOCKS, 256>>>(A);
    k_y<<<NN, 256>>>();
    k_final<<<NN, 256>>>(bg, out);
}

// round 6
// speedup vs baseline: 1.5922x; 1.2448x over previous
#include <cuda_runtime.h>

// ---------------------------------------------------------------------------
// GTN forward, round 5.
//   k_pre  : blocks [0,256): XW = X @ Wg (32x64 tiles, coalesced As loads)
//            blocks [256,264): zero g_nnz + softmax edge weights
//   k_scan : streaming sparsify of A — 16 independent __ldcs loads/thread
//   k_y    : Y[c] = A2[c] @ XW (unroll-8 sparse gather)
//   k_final: dense smem H row (warp scatter w/ prefetched nnz), threshold,
//            out = relu(coef * (A1 . Y - dropped corrections) + bg)
// ---------------------------------------------------------------------------

#define NN 2048
#define NE 4
#define NC 2
#define WIN 512
#define WOUT 256
#define CAP 128
#define MAXDROP 128
#define THRESH 0.05f
#define WEPS 1e-4f

#define PLANE4 ((size_t)NN * NN / 4)    // float4 per plane = 1048576
#define QUART4 (PLANE4 / 4)             // 262144
#define SCAN_BLOCKS 1024                // 1024*256 = QUART4 threads
#define GEMM_BLOCKS 256                 // (2048/32)*(256/64)

// Scratch (device globals; no allocations allowed)
__device__ float4 g_f1v[NC];            // softmaxed edge weights, channel-major
__device__ float4 g_f2v[NC];
__device__ int    g_nnz[NN];
__device__ int    g_cols[NN * CAP];
__device__ float2 g_a1[NN * CAP];       // (.x,.y) = channel 0,1
__device__ float2 g_a2[NN * CAP];
__device__ float  g_XW[NN * WOUT];
__device__ float  g_Y[NC][NN * WOUT];

// ---------------------------------------------------------------- k_pre
__global__ void __launch_bounds__(256) k_pre(const float* __restrict__ X,
                                             const float* __restrict__ Wg,
                                             const float* __restrict__ W1a,
                                             const float* __restrict__ W1b) {
    __shared__ float As[16][33];        // padded: conflict-free transposed store
    __shared__ float Bs[16][64];
    const int tid = threadIdx.x;

    if (blockIdx.x >= GEMM_BLOCKS) {
        // ---------------------------------- init role: zero nnz + softmax
        int t = (blockIdx.x - GEMM_BLOCKS) * 256 + tid;
        if (t < NN) g_nnz[t] = 0;
        if (blockIdx.x == GEMM_BLOCKS && tid == 0) {
            for (int c = 0; c < NC; c++) {
                float m = -1e30f;
                for (int e = 0; e < NE; e++) m = fmaxf(m, W1a[c * NE + e]);
                float ex[NE], s = 0.f;
                for (int e = 0; e < NE; e++) { ex[e] = expf(W1a[c * NE + e] - m); s += ex[e]; }
                float f[NE];
                for (int e = 0; e < NE; e++) {
                    float w = ex[e] / s;
                    f[e] = (w < WEPS) ? 0.f : w;
                }
                g_f1v[c] = make_float4(f[0], f[1], f[2], f[3]);

                m = -1e30f;
                for (int e = 0; e < NE; e++) m = fmaxf(m, W1b[c * NE + e]);
                s = 0.f;
                for (int e = 0; e < NE; e++) { ex[e] = expf(W1b[c * NE + e] - m); s += ex[e]; }
                for (int e = 0; e < NE; e++) {
                    float w = ex[e] / s;
                    f[e] = (w < WEPS) ? 0.f : w;
                }
                g_f2v[c] = make_float4(f[0], f[1], f[2], f[3]);
            }
        }
        return;
    }

    // -------------------------------------- GEMM role: XW = X @ Wg
    const int b  = blockIdx.x;
    const int bm = (b >> 2) * 32;
    const int bn = (b & 3) * 64;
    const int tx = tid & 15;            // n / 4
    const int ty = tid >> 4;            // 0..15, 2 m-rows each
    float acc[2][4] = {};

    for (int k0 = 0; k0 < WIN; k0 += 16) {
        // As: consecutive tid -> consecutive k (coalesced 64B per 16 thr)
        #pragma unroll
        for (int t = 0; t < 2; t++) {
            int idx = tid + t * 256;
            int kk = idx & 15, m = idx >> 4;
            As[kk][m] = X[(size_t)(bm + m) * WIN + k0 + kk];
        }
        // Bs: consecutive tid -> consecutive n (coalesced)
        #pragma unroll
        for (int t = 0; t < 4; t++) {
            int idx = tid + t * 256;
            int n = idx & 63, kk = idx >> 6;
            Bs[kk][n] = Wg[(size_t)(k0 + kk) * WOUT + bn + n];
        }
        __syncthreads();
        #pragma unroll
        for (int k = 0; k < 16; k++) {
            float a0 = As[k][ty * 2 + 0];
            float a1 = As[k][ty * 2 + 1];
            float4 b4 = *(const float4*)&Bs[k][tx * 4];
            acc[0][0] = fmaf(a0, b4.x, acc[0][0]);
            acc[0][1] = fmaf(a0, b4.y, acc[0][1]);
            acc[0][2] = fmaf(a0, b4.z, acc[0][2]);
            acc[0][3] = fmaf(a0, b4.w, acc[0][3]);
            acc[1][0] = fmaf(a1, b4.x, acc[1][0]);
            acc[1][1] = fmaf(a1, b4.y, acc[1][1]);
            acc[1][2] = fmaf(a1, b4.z, acc[1][2]);
            acc[1][3] = fmaf(a1, b4.w, acc[1][3]);
        }
        __syncthreads();
    }
    #pragma unroll
    for (int u = 0; u < 2; u++) {
        float4 o = make_float4(acc[u][0], acc[u][1], acc[u][2], acc[u][3]);
        *(float4*)&g_XW[(size_t)(bm + ty * 2 + u) * WOUT + bn + tx * 4] = o;
    }
}

// ---------------------------------------------------------------- k_scan
__device__ __forceinline__ void scan_emit(int i, int j,
                                          float a0, float a1, float a2, float a3,
                                          const float4& f1a, const float4& f1b,
                                          const float4& f2a, const float4& f2b) {
    bool nz = (a0 != 0.f) | (a1 != 0.f) | (a2 != 0.f) | (a3 != 0.f);
    if (nz) {
        int slot = atomicAdd(&g_nnz[i], 1);
        if (slot < CAP) {
            int idx = i * CAP + slot;
            g_cols[idx] = j;
            g_a1[idx] = make_float2(
                f1a.x * a0 + f1a.y * a1 + f1a.z * a2 + f1a.w * a3,
                f1b.x * a0 + f1b.y * a1 + f1b.z * a2 + f1b.w * a3);
            g_a2[idx] = make_float2(
                f2a.x * a0 + f2a.y * a1 + f2a.z * a2 + f2a.w * a3,
                f2b.x * a0 + f2b.y * a1 + f2b.z * a2 + f2b.w * a3);
        }
    }
}

__device__ __forceinline__ void scan_quad(size_t p,
                                          const float4& v0, const float4& v1,
                                          const float4& v2, const float4& v3,
                                          const float4& f1a, const float4& f1b,
                                          const float4& f2a, const float4& f2b) {
    // fast path: all 16 values zero (common case ~83%)
    if ((v0.x == 0.f) & (v0.y == 0.f) & (v0.z == 0.f) & (v0.w == 0.f) &
        (v1.x == 0.f) & (v1.y == 0.f) & (v1.z == 0.f) & (v1.w == 0.f) &
        (v2.x == 0.f) & (v2.y == 0.f) & (v2.z == 0.f) & (v2.w == 0.f) &
        (v3.x == 0.f) & (v3.y == 0.f) & (v3.z == 0.f) & (v3.w == 0.f))
        return;
    int i = (int)(p >> 9);              // 512 float4 per row
    int j0 = ((int)p & 511) * 4;
    scan_emit(i, j0 + 0, v0.x, v1.x, v2.x, v3.x, f1a, f1b, f2a, f2b);
    scan_emit(i, j0 + 1, v0.y, v1.y, v2.y, v3.y, f1a, f1b, f2a, f2b);
    scan_emit(i, j0 + 2, v0.z, v1.z, v2.z, v3.z, f1a, f1b, f2a, f2b);
    scan_emit(i, j0 + 3, v0.w, v1.w, v2.w, v3.w, f1a, f1b, f2a, f2b);
}

__global__ void __launch_bounds__(256) k_scan(const float* __restrict__ A) {
    const size_t t = (size_t)blockIdx.x * 256 + threadIdx.x;   // 0..QUART4-1
    const float4* base = (const float4*)A;

    const float4 f1a = g_f1v[0], f1b = g_f1v[1];
    const float4 f2a = g_f2v[0], f2b = g_f2v[1];

    // 16 fully independent streaming loads in one batch
    float4 v[4][4];
    #pragma unroll
    for (int q = 0; q < 4; q++) {
        size_t p = t + (size_t)q * QUART4;
        #pragma unroll
        for (int e = 0; e < 4; e++)
            v[q][e] = __ldcs(base + p + (size_t)e * PLANE4);
    }
    #pragma unroll
    for (int q = 0; q < 4; q++)
        scan_quad(t + (size_t)q * QUART4, v[q][0], v[q][1], v[q][2], v[q][3],
                  f1a, f1b, f2a, f2b);
}

// ---------------------------------------------------------------- k_y
__global__ void __launch_bounds__(256) k_y() {
    const int k = blockIdx.x;
    const int f = threadIdx.x;
    __shared__ int   scol[CAP];
    __shared__ float sv0[CAP], sv1[CAP];
    const int n2 = min(g_nnz[k], CAP);
    for (int s = f; s < n2; s += 256) {
        int idx = k * CAP + s;
        scol[s] = g_cols[idx] * WOUT;
        float2 a = g_a2[idx];
        sv0[s] = a.x;
        sv1[s] = a.y;
    }
    __syncthreads();
    float acc0 = 0.f, acc1 = 0.f;
    int s = 0;
    for (; s + 8 <= n2; s += 8) {
        float x[8];
        #pragma unroll
        for (int u = 0; u < 8; u++) x[u] = __ldg(&g_XW[scol[s + u] + f]);
        #pragma unroll
        for (int u = 0; u < 8; u++) {
            acc0 = fmaf(sv0[s + u], x[u], acc0);
            acc1 = fmaf(sv1[s + u], x[u], acc1);
        }
    }
    for (; s + 4 <= n2; s += 4) {
        float x[4];
        #pragma unroll
        for (int u = 0; u < 4; u++) x[u] = __ldg(&g_XW[scol[s + u] + f]);
        #pragma unroll
        for (int u = 0; u < 4; u++) {
            acc0 = fmaf(sv0[s + u], x[u], acc0);
            acc1 = fmaf(sv1[s + u], x[u], acc1);
        }
    }
    for (; s < n2; s++) {
        float x = __ldg(&g_XW[scol[s] + f]);
        acc0 = fmaf(sv0[s], x, acc0);
        acc1 = fmaf(sv1[s], x, acc1);
    }
    g_Y[0][(size_t)k * WOUT + f] = acc0;
    g_Y[1][(size_t)k * WOUT + f] = acc1;
}

// ---------------------------------------------------------------- k_final
__global__ void __launch_bounds__(256) k_final(const float* __restrict__ bg,
                                               float* __restrict__ out) {
    const int i = blockIdx.x;
    const int tid = threadIdx.x;
    const int warp = tid >> 5, lane = tid & 31;

    __shared__ float H0[NN], H1[NN];
    __shared__ int   offs[CAP];          // c1*WOUT
    __shared__ int   n2s[CAP];           // prefetched neighbor nnz
    __shared__ float w0s[CAP], w1s[CAP];
    __shared__ float degsh[NC];
    __shared__ int   dropn[NC];
    __shared__ int   dropj[NC][MAXDROP];
    __shared__ float droph[NC][MAXDROP];

    float4 z = make_float4(0.f, 0.f, 0.f, 0.f);
    for (int t = tid; t < NN / 4; t += 256) {
        ((float4*)H0)[t] = z;
        ((float4*)H1)[t] = z;
    }
    if (tid < NC) { degsh[tid] = 0.f; dropn[tid] = 0; }
    const int n1 = min(g_nnz[i], CAP);
    for (int s = tid; s < n1; s += 256) {
        int idx = i * CAP + s;
        int c = g_cols[idx];
        offs[s] = c * WOUT;
        n2s[s] = min(g_nnz[c], CAP);
        float2 a = g_a1[idx];
        w0s[s] = a.x;
        w1s[s] = a.y;
    }
    __syncthreads();

    // scatter: one warp per source slot s, lanes over target slots s2
    for (int s = warp; s < n1; s += 8) {
        int kbase = (offs[s] / WOUT) * CAP;
        int n2 = n2s[s];
        float w0 = w0s[s], w1 = w1s[s];
        for (int s2 = lane; s2 < n2; s2 += 32) {
            int idx = kbase + s2;
            int j = g_cols[idx];
            float2 a = g_a2[idx];
            float h0 = w0 * a.x;
            float h1 = w1 * a.y;
            if (h0 != 0.f) atomicAdd(&H0[j], h0);
            if (h1 != 0.f) atomicAdd(&H1[j], h1);
        }
    }
    __syncthreads();

    // threshold scan: degree sums + dropped-entry lists
    float d0 = 0.f, d1 = 0.f;
    for (int j = tid; j < NN; j += 256) {
        float h0 = H0[j];
        if (h0 > THRESH) d0 += h0;
        else if (h0 > 0.f) {
            int p = atomicAdd(&dropn[0], 1);
            if (p < MAXDROP) { dropj[0][p] = j; droph[0][p] = h0; }
        }
        float h1 = H1[j];
        if (h1 > THRESH) d1 += h1;
        else if (h1 > 0.f) {
            int p = atomicAdd(&dropn[1], 1);
            if (p < MAXDROP) { dropj[1][p] = j; droph[1][p] = h1; }
        }
    }
    #pragma unroll
    for (int o = 16; o > 0; o >>= 1) {
        d0 += __shfl_down_sync(0xffffffff, d0, o);
        d1 += __shfl_down_sync(0xffffffff, d1, o);
    }
    if (lane == 0) {
        if (d0 != 0.f) atomicAdd(&degsh[0], d0);
        if (d1 != 0.f) atomicAdd(&degsh[1], d1);
    }
    __syncthreads();

    float coef[NC];
    #pragma unroll
    for (int c = 0; c < NC; c++) {
        float deg = degsh[c];
        if (deg > 0.f) {
            float dinv = 1.f / deg;
            float deg2 = deg * dinv;     // double row-normalization
            coef[c] = dinv * (1.f / deg2);
        } else {
            coef[c] = 0.f;
        }
    }

    // output: feature f = tid; interleave channel gathers (8 loads in flight)
    const int f = tid;
    const float bias = bg[f];
    const float* Y0 = g_Y[0];
    const float* Y1 = g_Y[1];
    float acc0 = 0.f, acc1 = 0.f;
    int s = 0;
    for (; s + 4 <= n1; s += 4) {
        int o0 = offs[s + 0] + f, o1 = offs[s + 1] + f;
        int o2 = offs[s + 2] + f, o3 = offs[s + 3] + f;
        float a0 = __ldg(Y0 + o0), b0 = __ldg(Y1 + o0);
        float a1 = __ldg(Y0 + o1), b1 = __ldg(Y1 + o1);
        float a2 = __ldg(Y0 + o2), b2 = __ldg(Y1 + o2);
        float a3 = __ldg(Y0 + o3), b3 = __ldg(Y1 + o3);
        acc0 = fmaf(w0s[s + 0], a0, acc0); acc1 = fmaf(w1s[s + 0], b0, acc1);
        acc0 = fmaf(w0s[s + 1], a1, acc0); acc1 = fmaf(w1s[s + 1], b1, acc1);
        acc0 = fmaf(w0s[s + 2], a2, acc0); acc1 = fmaf(w1s[s + 2], b2, acc1);
        acc0 = fmaf(w0s[s + 3], a3, acc0); acc1 = fmaf(w1s[s + 3], b3, acc1);
    }
    for (; s < n1; s++) {
        int o = offs[s] + f;
        acc0 = fmaf(w0s[s], __ldg(Y0 + o), acc0);
        acc1 = fmaf(w1s[s], __ldg(Y1 + o), acc1);
    }

    int nd0 = min(dropn[0], MAXDROP);
    for (int d = 0; d < nd0; d++)
        acc0 -= droph[0][d] * g_XW[(size_t)dropj[0][d] * WOUT + f];
    int nd1 = min(dropn[1], MAXDROP);
    for (int d = 0; d < nd1; d++)
        acc1 -= droph[1][d] * g_XW[(size_t)dropj[1][d] * WOUT + f];

    float o0 = coef[0] * acc0 + bias;
    float o1 = coef[1] * acc1 + bias;
    out[(size_t)i * (NC * WOUT) + f]        = fmaxf(o0, 0.f);
    out[(size_t)i * (NC * WOUT) + WOUT + f] = fmaxf(o1, 0.f);
}

// ---------------------------------------------------------------------------
extern "C" void kernel_launch(void* const* d_in, const int* in_sizes, int n_in,
                              void* d_out, int out_size) {
    const float* A   = (const float*)d_in[0];
    const float* X   = (const float*)d_in[1];
    const float* W1a = (const float*)d_in[2];
    const float* W1b = (const float*)d_in[3];
    const float* Wg  = (const float*)d_in[4];
    const float* bg  = (const float*)d_in[5];
    float* out = (float*)d_out;

    k_pre<<<GEMM_BLOCKS + 8, 256>>>(X, Wg, W1a, W1b);
    k_scan<<<SCAN_BLOCKS, 256>>>(A);
    k_y<<<NN, 256>>>();
    k_final<<<NN, 256>>>(bg, out);
}